// round 6
// baseline (speedup 1.0000x reference)
#include <cuda_runtime.h>
#include <cfloat>
#include <math.h>

// Problem constants
#define NN 16384
#define MM 32768
#define KK 8
#define CC 256
#define GG 16                 // M-splits for KNN parallelism
#define MSEG (MM / GG)        // 2048
#define TILE 1024             // cond candidates per shared tile

// Scratch (device globals; no allocations allowed)
__device__ float g_pd[GG * NN * KK];   // partial top-8 squared dists
__device__ int   g_pi[GG * NN * KK];   // partial top-8 indices
__device__ float g_favg[NN * CC];      // weighted-average features
__device__ float g_h1[NN * CC];        // MLP intermediate 1
__device__ float g_h2[NN * CC];        // MLP intermediate 2
__device__ float g_tf[CC];             // timestep feature vector

// ---------------------------------------------------------------------------
// Kernel 1: timestep embedding -> 2-layer MLP -> g_tf[256]
// ---------------------------------------------------------------------------
__global__ void k_tfeats(const float* __restrict__ t,
                         const float* __restrict__ Wt1, const float* __restrict__ bt1,
                         const float* __restrict__ Wt2, const float* __restrict__ bt2) {
    __shared__ float emb[96];
    __shared__ float h1[96];
    int tid = threadIdx.x;
    float tv = t[0];
    if (tid < 48) {
        const double c64 = -9.210340371976184 / 47.0;
        float cf = (float)c64;
        float arg = __fmul_rn((float)tid, cf);
        float f = (float)exp((double)arg);
        float e = __fmul_rn(tv, f);
        emb[tid]      = (float)sin((double)e);
        emb[tid + 48] = (float)cos((double)e);
    }
    __syncthreads();
    if (tid < 96) {
        float acc = 0.0f;
        #pragma unroll 8
        for (int j = 0; j < 96; ++j) acc += emb[j] * Wt1[tid * 96 + j];
        acc += bt1[tid];
        h1[tid] = (acc >= 0.0f) ? acc : 0.1f * acc;
    }
    __syncthreads();
    if (tid < 256) {
        float acc = 0.0f;
        #pragma unroll 8
        for (int j = 0; j < 96; ++j) acc += h1[j] * Wt2[tid * 96 + j];
        acc += bt2[tid];
        g_tf[tid] = acc;
    }
}

// ---------------------------------------------------------------------------
// Packed f32x2 helpers (two independent IEEE-RN fp32 lanes -> bit-exact)
// ---------------------------------------------------------------------------
__device__ __forceinline__ unsigned long long pack2(float x) {
    unsigned long long r;
    asm("mov.b64 %0, {%1, %1};" : "=l"(r) : "f"(x));
    return r;
}

// d_lane = fma(dz,dz, fma(dy,dy, dx*dx)) with dx = nx + (-cx)  (XLA scheme)
__device__ __forceinline__ void dist2x2(unsigned long long nx, unsigned long long ny,
                                        unsigned long long nz,
                                        unsigned long long cx, unsigned long long cy,
                                        unsigned long long cz,
                                        float& d0, float& d1) {
    asm("{\n\t"
        ".reg .b64 dx, dy, dz, t;\n\t"
        "add.rn.f32x2 dx, %2, %5;\n\t"
        "add.rn.f32x2 dy, %3, %6;\n\t"
        "add.rn.f32x2 dz, %4, %7;\n\t"
        "mul.rn.f32x2 t, dx, dx;\n\t"
        "fma.rn.f32x2 t, dy, dy, t;\n\t"
        "fma.rn.f32x2 t, dz, dz, t;\n\t"
        "mov.b64 {%0, %1}, t;\n\t"
        "}"
        : "=f"(d0), "=f"(d1)
        : "l"(nx), "l"(ny), "l"(nz), "l"(cx), "l"(cy), "l"(cz));
}

__device__ __forceinline__ void insert8(float d, int idx, float* bd, int* bi) {
    if (d < bd[KK - 1]) {
        bd[KK - 1] = d;
        bi[KK - 1] = idx;
        #pragma unroll
        for (int q = KK - 1; q > 0; --q) {
            if (bd[q] < bd[q - 1]) {
                float td = bd[q]; bd[q] = bd[q - 1]; bd[q - 1] = td;
                int   ti = bi[q]; bi[q] = bi[q - 1]; bi[q - 1] = ti;
            }
        }
    }
}

union F4U {
    float4 v;
    unsigned long long u[2];
};

// ---------------------------------------------------------------------------
// Kernel 2: brute-force KNN, exact XLA fmla scheme, packed f32x2.
// 2 nodes/thread, 4 candidates/iteration via LDS.128 (two packed halves).
// Pair-guard: fminf(d0,d1) < bd[7] -> conservative, no false negatives;
// survivors re-checked exactly by insert8 (identical fp + tie semantics).
// ---------------------------------------------------------------------------
__global__ void __launch_bounds__(128) k_knn(const int* __restrict__ node_c,
                                             const int* __restrict__ cond_c) {
    __shared__ __align__(16) float s_nx[TILE];
    __shared__ __align__(16) float s_ny[TILE];
    __shared__ __align__(16) float s_nz[TILE];

    const int tid = threadIdx.x;
    const int n0 = blockIdx.x * 256 + tid;
    const int n1 = n0 + 128;

    const int4 ncA = ((const int4*)node_c)[n0];
    const int4 ncB = ((const int4*)node_c)[n1];
    unsigned long long nxA = pack2(__fmul_rn(__fadd_rn((float)ncA.y, 8.0f), 0.05f));
    unsigned long long nyA = pack2(__fmul_rn(__fadd_rn((float)ncA.z, 8.0f), 0.05f));
    unsigned long long nzA = pack2(__fmul_rn(__fadd_rn((float)ncA.w, 8.0f), 0.05f));
    unsigned long long nxB = pack2(__fmul_rn(__fadd_rn((float)ncB.y, 8.0f), 0.05f));
    unsigned long long nyB = pack2(__fmul_rn(__fadd_rn((float)ncB.z, 8.0f), 0.05f));
    unsigned long long nzB = pack2(__fmul_rn(__fadd_rn((float)ncB.w, 8.0f), 0.05f));

    float bdA[KK], bdB[KK];
    int   biA[KK], biB[KK];
    #pragma unroll
    for (int s = 0; s < KK; ++s) {
        bdA[s] = FLT_MAX; biA[s] = 0x7fffffff;
        bdB[s] = FLT_MAX; biB[s] = 0x7fffffff;
    }

    const int m0 = blockIdx.y * MSEG;

    for (int t0 = 0; t0 < MSEG; t0 += TILE) {
        // negated transformed candidate coords, SoA
        for (int j = tid; j < TILE; j += 128) {
            int4 cc = ((const int4*)cond_c)[m0 + t0 + j];
            s_nx[j] = -__fmul_rn(__fadd_rn((float)cc.y, 0.5f), 0.01f);
            s_ny[j] = -__fmul_rn(__fadd_rn((float)cc.z, 0.5f), 0.01f);
            s_nz[j] = -__fmul_rn(__fadd_rn((float)cc.w, 0.5f), 0.01f);
        }
        __syncthreads();

        #pragma unroll 2
        for (int j = 0; j < TILE; j += 4) {
            F4U X, Y, Z;
            X.v = *(const float4*)&s_nx[j];
            Y.v = *(const float4*)&s_ny[j];
            Z.v = *(const float4*)&s_nz[j];

            float dA0, dA1, dA2, dA3, dB0, dB1, dB2, dB3;
            dist2x2(nxA, nyA, nzA, X.u[0], Y.u[0], Z.u[0], dA0, dA1);
            dist2x2(nxA, nyA, nzA, X.u[1], Y.u[1], Z.u[1], dA2, dA3);
            dist2x2(nxB, nyB, nzB, X.u[0], Y.u[0], Z.u[0], dB0, dB1);
            dist2x2(nxB, nyB, nzB, X.u[1], Y.u[1], Z.u[1], dB2, dB3);

            int g = m0 + t0 + j;
            if (fminf(dA0, dA1) < bdA[KK - 1]) { insert8(dA0, g,     bdA, biA); insert8(dA1, g + 1, bdA, biA); }
            if (fminf(dA2, dA3) < bdA[KK - 1]) { insert8(dA2, g + 2, bdA, biA); insert8(dA3, g + 3, bdA, biA); }
            if (fminf(dB0, dB1) < bdB[KK - 1]) { insert8(dB0, g,     bdB, biB); insert8(dB1, g + 1, bdB, biB); }
            if (fminf(dB2, dB3) < bdB[KK - 1]) { insert8(dB2, g + 2, bdB, biB); insert8(dB3, g + 3, bdB, biB); }
        }
        __syncthreads();
    }

    int baseA = (blockIdx.y * NN + n0) * KK;
    int baseB = (blockIdx.y * NN + n1) * KK;
    #pragma unroll
    for (int s = 0; s < KK; ++s) {
        g_pd[baseA + s] = bdA[s];  g_pi[baseA + s] = biA[s];
        g_pd[baseB + s] = bdB[s];  g_pi[baseB + s] = biB[s];
    }
}

// ---------------------------------------------------------------------------
// Kernel 3: merge GG x 8 = 128 partials -> top-8, weights, weighted gather.
// One warp per node; lane owns entries lane, lane+32, lane+64, lane+96.
// ---------------------------------------------------------------------------
__global__ void __launch_bounds__(256) k_merge(const float* __restrict__ cond_feats) {
    int warp = threadIdx.x >> 5;
    int lane = threadIdx.x & 31;
    int n = blockIdx.x * 8 + warp;

    float d[4];
    int   id[4];
    #pragma unroll
    for (int q = 0; q < 4; ++q) {
        int e = lane + q * 32;
        int src = ((e >> 3) * NN + n) * KK + (e & 7);
        d[q]  = g_pd[src];
        id[q] = g_pi[src];
    }

    float wd[KK];
    int   wi[KK];
    #pragma unroll
    for (int k = 0; k < KK; ++k) {
        float cd = d[0]; int ci = id[0];
        #pragma unroll
        for (int q = 1; q < 4; ++q) {
            if (d[q] < cd || (d[q] == cd && id[q] < ci)) { cd = d[q]; ci = id[q]; }
        }
        #pragma unroll
        for (int off = 16; off > 0; off >>= 1) {
            float od = __shfl_xor_sync(0xffffffffu, cd, off);
            int   oi = __shfl_xor_sync(0xffffffffu, ci, off);
            if (od < cd || (od == cd && oi < ci)) { cd = od; ci = oi; }
        }
        wd[k] = cd; wi[k] = ci;
        #pragma unroll
        for (int q = 0; q < 4; ++q) if (id[q] == ci) d[q] = FLT_MAX;
    }

    float w[KK];
    float wsum = 0.0f;
    #pragma unroll
    for (int k = 0; k < KK; ++k) {
        float dist = fmaxf(sqrtf(wd[k]), 1e-6f);
        w[k] = 1.0f / dist;
        wsum += w[k];
    }
    #pragma unroll
    for (int k = 0; k < KK; ++k) w[k] = w[k] / wsum;

    const float* rp[KK];
    #pragma unroll
    for (int k = 0; k < KK; ++k) rp[k] = cond_feats + (size_t)wi[k] * CC;

    float* outp = g_favg + (size_t)n * CC;
    #pragma unroll
    for (int j = 0; j < 8; ++j) {
        int c = lane + j * 32;
        float acc = 0.0f;
        #pragma unroll
        for (int k = 0; k < KK; ++k) acc = fmaf(w[k], rp[k][c], acc);
        outp[c] = acc;
    }
}

// ---------------------------------------------------------------------------
// Kernel 4: register-blocked SGEMM  Y[16384,256] = X @ W^T (+bias, act, tf)
// 128x64 tile, 256 threads, 4x8 micro-tile, double-buffered smem.
// More blocks (512) than the old 128x128 version -> better latency hiding.
// ---------------------------------------------------------------------------
#define SPA 132   // A smem pitch (128 rows + pad)
#define SPB 68    // B smem pitch (64 cols + pad)
template<int ACT, int ADDTF>
__global__ void __launch_bounds__(256, 3) k_gemm(const float* __restrict__ X,
                                                 const float* __restrict__ W,
                                                 const float* __restrict__ bias,
                                                 float* __restrict__ Y) {
    __shared__ float As[2][8][SPA];
    __shared__ float Bs[2][8][SPB];

    const int t   = threadIdx.x;
    const int tx  = t & 7;           // 8 col groups of 8
    const int ty  = t >> 3;          // 32 row groups of 4
    const int row0 = blockIdx.x * 128;
    const int col0 = blockIdx.y * 64;

    // A loads: all 256 threads, one float4 each per k-tile
    const int arow = t >> 1;
    const int ak4  = (t & 1) * 4;
    const float* Ag = X + (size_t)(row0 + arow) * CC + ak4;
    // B loads: threads 0..127, one float4 each per k-tile
    const int brow = (t & 127) >> 1;
    const int bk4  = (t & 1) * 4;
    const float* Bg = W + (size_t)(col0 + brow) * CC + bk4;
    const bool bload = (t < 128);

    float4 afrag = *(const float4*)Ag;
    float4 bfrag = bload ? *(const float4*)Bg : make_float4(0.f, 0.f, 0.f, 0.f);

    As[0][ak4 + 0][arow] = afrag.x;
    As[0][ak4 + 1][arow] = afrag.y;
    As[0][ak4 + 2][arow] = afrag.z;
    As[0][ak4 + 3][arow] = afrag.w;
    if (bload) {
        Bs[0][bk4 + 0][brow] = bfrag.x;
        Bs[0][bk4 + 1][brow] = bfrag.y;
        Bs[0][bk4 + 2][brow] = bfrag.z;
        Bs[0][bk4 + 3][brow] = bfrag.w;
    }
    __syncthreads();

    float acc[4][8];
    #pragma unroll
    for (int i = 0; i < 4; ++i)
        #pragma unroll
        for (int j = 0; j < 8; ++j) acc[i][j] = 0.0f;

    #pragma unroll 1
    for (int kt = 0; kt < 32; ++kt) {
        int buf = kt & 1;
        if (kt < 31) {
            afrag = *(const float4*)(Ag + (kt + 1) * 8);
            if (bload) bfrag = *(const float4*)(Bg + (kt + 1) * 8);
        }

        #pragma unroll
        for (int kk = 0; kk < 8; ++kk) {
            float4 a  = *(const float4*)&As[buf][kk][ty * 4];
            float4 b0 = *(const float4*)&Bs[buf][kk][tx * 8];
            float4 b1 = *(const float4*)&Bs[buf][kk][tx * 8 + 4];
            float av[4] = {a.x, a.y, a.z, a.w};
            float bv[8] = {b0.x, b0.y, b0.z, b0.w, b1.x, b1.y, b1.z, b1.w};
            #pragma unroll
            for (int i = 0; i < 4; ++i)
                #pragma unroll
                for (int j = 0; j < 8; ++j)
                    acc[i][j] = fmaf(av[i], bv[j], acc[i][j]);
        }

        if (kt < 31) {
            int nb = buf ^ 1;
            As[nb][ak4 + 0][arow] = afrag.x;
            As[nb][ak4 + 1][arow] = afrag.y;
            As[nb][ak4 + 2][arow] = afrag.z;
            As[nb][ak4 + 3][arow] = afrag.w;
            if (bload) {
                Bs[nb][bk4 + 0][brow] = bfrag.x;
                Bs[nb][bk4 + 1][brow] = bfrag.y;
                Bs[nb][bk4 + 2][brow] = bfrag.z;
                Bs[nb][bk4 + 3][brow] = bfrag.w;
            }
            __syncthreads();
        }
    }

    float bb[8], tf[8];
    #pragma unroll
    for (int j = 0; j < 8; ++j) {
        int c = col0 + tx * 8 + j;
        bb[j] = bias[c];
        if (ADDTF) tf[j] = g_tf[c];
    }

    #pragma unroll
    for (int i = 0; i < 4; ++i) {
        int r = row0 + ty * 4 + i;
        float o[8];
        #pragma unroll
        for (int j = 0; j < 8; ++j) {
            float v = acc[i][j] + bb[j];
            if (ACT)   v = (v >= 0.0f) ? v : 0.1f * v;
            if (ADDTF) v = v + tf[j];
            o[j] = v;
        }
        float4* yp = (float4*)(Y + (size_t)r * CC + col0 + tx * 8);
        yp[0] = make_float4(o[0], o[1], o[2], o[3]);
        yp[1] = make_float4(o[4], o[5], o[6], o[7]);
    }
}

// ---------------------------------------------------------------------------
extern "C" void kernel_launch(void* const* d_in, const int* in_sizes, int n_in,
                              void* d_out, int out_size) {
    const int*   node_c     = (const int*)d_in[0];
    const int*   cond_c     = (const int*)d_in[1];
    const float* cond_feats = (const float*)d_in[2];
    const float* t          = (const float*)d_in[3];
    const float* W_proj     = (const float*)d_in[4];
    const float* b_proj     = (const float*)d_in[5];
    const float* W_l1       = (const float*)d_in[6];
    const float* b_l1       = (const float*)d_in[7];
    const float* W_l2       = (const float*)d_in[8];
    const float* b_l2       = (const float*)d_in[9];
    const float* W_t1       = (const float*)d_in[10];
    const float* b_t1       = (const float*)d_in[11];
    const float* W_t2       = (const float*)d_in[12];
    const float* b_t2       = (const float*)d_in[13];
    float* out = (float*)d_out;

    float* h1; cudaGetSymbolAddress((void**)&h1, g_h1);
    float* h2; cudaGetSymbolAddress((void**)&h2, g_h2);
    float* fa; cudaGetSymbolAddress((void**)&fa, g_favg);

    k_tfeats<<<1, 256>>>(t, W_t1, b_t1, W_t2, b_t2);

    dim3 gknn(NN / 256, GG);       // 64 x 16 blocks, 128 threads (2 nodes/thread)
    k_knn<<<gknn, 128>>>(node_c, cond_c);

    k_merge<<<NN / 8, 256>>>(cond_feats);

    dim3 gg(NN / 128, CC / 64);    // 128 x 4 = 512 blocks
    k_gemm<0, 0><<<gg, 256>>>(fa, W_proj, b_proj, h1);
    k_gemm<1, 0><<<gg, 256>>>(h1, W_l1, b_l1, h2);
    k_gemm<0, 1><<<gg, 256>>>(h2, W_l2, b_l2, out);

    (void)in_sizes; (void)n_in; (void)out_size;
}

// round 7
// speedup vs baseline: 1.2420x; 1.2420x over previous
#include <cuda_runtime.h>
#include <cfloat>
#include <math.h>

// Problem constants
#define NN 16384
#define MM 32768
#define KK 8
#define CC 256
#define GG 16                 // M-splits for KNN parallelism
#define MSEG (MM / GG)        // 2048
#define TILE 1024             // cond candidates per shared tile

// Scratch (device globals; no allocations allowed)
__device__ float g_pd[GG * NN * KK];   // partial top-8 squared dists
__device__ int   g_pi[GG * NN * KK];   // partial top-8 indices
__device__ float g_favg[NN * CC];      // weighted-average features
__device__ float g_h1[NN * CC];        // MLP intermediate 1
__device__ float g_h2[NN * CC];        // MLP intermediate 2
__device__ float g_tf[CC];             // timestep feature vector

// ---------------------------------------------------------------------------
// Kernel 1: timestep embedding -> 2-layer MLP -> g_tf[256]
// ---------------------------------------------------------------------------
__global__ void k_tfeats(const float* __restrict__ t,
                         const float* __restrict__ Wt1, const float* __restrict__ bt1,
                         const float* __restrict__ Wt2, const float* __restrict__ bt2) {
    __shared__ float emb[96];
    __shared__ float h1[96];
    int tid = threadIdx.x;
    float tv = t[0];
    if (tid < 48) {
        const double c64 = -9.210340371976184 / 47.0;
        float cf = (float)c64;
        float arg = __fmul_rn((float)tid, cf);
        float f = (float)exp((double)arg);
        float e = __fmul_rn(tv, f);
        emb[tid]      = (float)sin((double)e);
        emb[tid + 48] = (float)cos((double)e);
    }
    __syncthreads();
    if (tid < 96) {
        float acc = 0.0f;
        #pragma unroll 8
        for (int j = 0; j < 96; ++j) acc += emb[j] * Wt1[tid * 96 + j];
        acc += bt1[tid];
        h1[tid] = (acc >= 0.0f) ? acc : 0.1f * acc;
    }
    __syncthreads();
    if (tid < 256) {
        float acc = 0.0f;
        #pragma unroll 8
        for (int j = 0; j < 96; ++j) acc += h1[j] * Wt2[tid * 96 + j];
        acc += bt2[tid];
        g_tf[tid] = acc;
    }
}

// ---------------------------------------------------------------------------
// Packed f32x2 helpers (two independent IEEE-RN fp32 lanes -> bit-exact)
// ---------------------------------------------------------------------------
__device__ __forceinline__ unsigned long long pack2(float x) {
    unsigned long long r;
    asm("mov.b64 %0, {%1, %1};" : "=l"(r) : "f"(x));
    return r;
}

// d_lane = fma(dz,dz, fma(dy,dy, dx*dx)) with dx = nx + (-cx)  (XLA scheme)
__device__ __forceinline__ void dist2x2(unsigned long long nx, unsigned long long ny,
                                        unsigned long long nz,
                                        unsigned long long cx, unsigned long long cy,
                                        unsigned long long cz,
                                        float& d0, float& d1) {
    asm("{\n\t"
        ".reg .b64 dx, dy, dz, t;\n\t"
        "add.rn.f32x2 dx, %2, %5;\n\t"
        "add.rn.f32x2 dy, %3, %6;\n\t"
        "add.rn.f32x2 dz, %4, %7;\n\t"
        "mul.rn.f32x2 t, dx, dx;\n\t"
        "fma.rn.f32x2 t, dy, dy, t;\n\t"
        "fma.rn.f32x2 t, dz, dz, t;\n\t"
        "mov.b64 {%0, %1}, t;\n\t"
        "}"
        : "=f"(d0), "=f"(d1)
        : "l"(nx), "l"(ny), "l"(nz), "l"(cx), "l"(cy), "l"(cz));
}

__device__ __forceinline__ void insert8(float d, int idx, float* bd, int* bi) {
    if (d < bd[KK - 1]) {
        bd[KK - 1] = d;
        bi[KK - 1] = idx;
        #pragma unroll
        for (int q = KK - 1; q > 0; --q) {
            if (bd[q] < bd[q - 1]) {
                float td = bd[q]; bd[q] = bd[q - 1]; bd[q - 1] = td;
                int   ti = bi[q]; bi[q] = bi[q - 1]; bi[q - 1] = ti;
            }
        }
    }
}

union F4U {
    float4 v;
    unsigned long long u[2];
};

// ---------------------------------------------------------------------------
// Kernel 2: brute-force KNN, exact XLA fmla scheme, packed f32x2.
// 2 nodes/thread, 4 candidates/iteration via LDS.128 (two packed halves).
// Pair-guard: fminf(d0,d1) < bd[7] -> conservative, no false negatives;
// survivors re-checked exactly by insert8 (identical fp + tie semantics).
// ---------------------------------------------------------------------------
__global__ void __launch_bounds__(128) k_knn(const int* __restrict__ node_c,
                                             const int* __restrict__ cond_c) {
    __shared__ __align__(16) float s_nx[TILE];
    __shared__ __align__(16) float s_ny[TILE];
    __shared__ __align__(16) float s_nz[TILE];

    const int tid = threadIdx.x;
    const int n0 = blockIdx.x * 256 + tid;
    const int n1 = n0 + 128;

    const int4 ncA = ((const int4*)node_c)[n0];
    const int4 ncB = ((const int4*)node_c)[n1];
    unsigned long long nxA = pack2(__fmul_rn(__fadd_rn((float)ncA.y, 8.0f), 0.05f));
    unsigned long long nyA = pack2(__fmul_rn(__fadd_rn((float)ncA.z, 8.0f), 0.05f));
    unsigned long long nzA = pack2(__fmul_rn(__fadd_rn((float)ncA.w, 8.0f), 0.05f));
    unsigned long long nxB = pack2(__fmul_rn(__fadd_rn((float)ncB.y, 8.0f), 0.05f));
    unsigned long long nyB = pack2(__fmul_rn(__fadd_rn((float)ncB.z, 8.0f), 0.05f));
    unsigned long long nzB = pack2(__fmul_rn(__fadd_rn((float)ncB.w, 8.0f), 0.05f));

    float bdA[KK], bdB[KK];
    int   biA[KK], biB[KK];
    #pragma unroll
    for (int s = 0; s < KK; ++s) {
        bdA[s] = FLT_MAX; biA[s] = 0x7fffffff;
        bdB[s] = FLT_MAX; biB[s] = 0x7fffffff;
    }

    const int m0 = blockIdx.y * MSEG;

    for (int t0 = 0; t0 < MSEG; t0 += TILE) {
        // negated transformed candidate coords, SoA
        for (int j = tid; j < TILE; j += 128) {
            int4 cc = ((const int4*)cond_c)[m0 + t0 + j];
            s_nx[j] = -__fmul_rn(__fadd_rn((float)cc.y, 0.5f), 0.01f);
            s_ny[j] = -__fmul_rn(__fadd_rn((float)cc.z, 0.5f), 0.01f);
            s_nz[j] = -__fmul_rn(__fadd_rn((float)cc.w, 0.5f), 0.01f);
        }
        __syncthreads();

        #pragma unroll 2
        for (int j = 0; j < TILE; j += 4) {
            F4U X, Y, Z;
            X.v = *(const float4*)&s_nx[j];
            Y.v = *(const float4*)&s_ny[j];
            Z.v = *(const float4*)&s_nz[j];

            float dA0, dA1, dA2, dA3, dB0, dB1, dB2, dB3;
            dist2x2(nxA, nyA, nzA, X.u[0], Y.u[0], Z.u[0], dA0, dA1);
            dist2x2(nxA, nyA, nzA, X.u[1], Y.u[1], Z.u[1], dA2, dA3);
            dist2x2(nxB, nyB, nzB, X.u[0], Y.u[0], Z.u[0], dB0, dB1);
            dist2x2(nxB, nyB, nzB, X.u[1], Y.u[1], Z.u[1], dB2, dB3);

            int g = m0 + t0 + j;
            if (fminf(dA0, dA1) < bdA[KK - 1]) { insert8(dA0, g,     bdA, biA); insert8(dA1, g + 1, bdA, biA); }
            if (fminf(dA2, dA3) < bdA[KK - 1]) { insert8(dA2, g + 2, bdA, biA); insert8(dA3, g + 3, bdA, biA); }
            if (fminf(dB0, dB1) < bdB[KK - 1]) { insert8(dB0, g,     bdB, biB); insert8(dB1, g + 1, bdB, biB); }
            if (fminf(dB2, dB3) < bdB[KK - 1]) { insert8(dB2, g + 2, bdB, biB); insert8(dB3, g + 3, bdB, biB); }
        }
        __syncthreads();
    }

    int baseA = (blockIdx.y * NN + n0) * KK;
    int baseB = (blockIdx.y * NN + n1) * KK;
    #pragma unroll
    for (int s = 0; s < KK; ++s) {
        g_pd[baseA + s] = bdA[s];  g_pi[baseA + s] = biA[s];
        g_pd[baseB + s] = bdB[s];  g_pi[baseB + s] = biB[s];
    }
}

// ---------------------------------------------------------------------------
// Kernel 3: merge GG x 8 = 128 partials -> top-8, weights, weighted gather.
// One warp per node; lane owns entries lane, lane+32, lane+64, lane+96.
// ---------------------------------------------------------------------------
__global__ void __launch_bounds__(256) k_merge(const float* __restrict__ cond_feats) {
    int warp = threadIdx.x >> 5;
    int lane = threadIdx.x & 31;
    int n = blockIdx.x * 8 + warp;

    float d[4];
    int   id[4];
    #pragma unroll
    for (int q = 0; q < 4; ++q) {
        int e = lane + q * 32;
        int src = ((e >> 3) * NN + n) * KK + (e & 7);
        d[q]  = g_pd[src];
        id[q] = g_pi[src];
    }

    float wd[KK];
    int   wi[KK];
    #pragma unroll
    for (int k = 0; k < KK; ++k) {
        float cd = d[0]; int ci = id[0];
        #pragma unroll
        for (int q = 1; q < 4; ++q) {
            if (d[q] < cd || (d[q] == cd && id[q] < ci)) { cd = d[q]; ci = id[q]; }
        }
        #pragma unroll
        for (int off = 16; off > 0; off >>= 1) {
            float od = __shfl_xor_sync(0xffffffffu, cd, off);
            int   oi = __shfl_xor_sync(0xffffffffu, ci, off);
            if (od < cd || (od == cd && oi < ci)) { cd = od; ci = oi; }
        }
        wd[k] = cd; wi[k] = ci;
        #pragma unroll
        for (int q = 0; q < 4; ++q) if (id[q] == ci) d[q] = FLT_MAX;
    }

    float w[KK];
    float wsum = 0.0f;
    #pragma unroll
    for (int k = 0; k < KK; ++k) {
        float dist = fmaxf(sqrtf(wd[k]), 1e-6f);
        w[k] = 1.0f / dist;
        wsum += w[k];
    }
    #pragma unroll
    for (int k = 0; k < KK; ++k) w[k] = w[k] / wsum;

    const float* rp[KK];
    #pragma unroll
    for (int k = 0; k < KK; ++k) rp[k] = cond_feats + (size_t)wi[k] * CC;

    float* outp = g_favg + (size_t)n * CC;
    #pragma unroll
    for (int j = 0; j < 8; ++j) {
        int c = lane + j * 32;
        float acc = 0.0f;
        #pragma unroll
        for (int k = 0; k < KK; ++k) acc = fmaf(w[k], rp[k][c], acc);
        outp[c] = acc;
    }
}

// ---------------------------------------------------------------------------
// Kernel 4: register-blocked SGEMM  Y[16384,256] = X @ W^T (+bias, act, tf)
// 128x128 tile, 256 threads, 8x8 micro-tile, double-buffered smem (proven
// fastest variant: 61us, fma 44%).
// ---------------------------------------------------------------------------
#define SP 132   // smem pitch (floats)
template<int ACT, int ADDTF>
__global__ void __launch_bounds__(256, 2) k_gemm(const float* __restrict__ X,
                                                 const float* __restrict__ W,
                                                 const float* __restrict__ bias,
                                                 float* __restrict__ Y) {
    __shared__ float As[2][8][SP];
    __shared__ float Bs[2][8][SP];

    const int t   = threadIdx.x;
    const int tx  = t & 15;
    const int ty  = t >> 4;
    const int row0 = blockIdx.x * 128;
    const int col0 = blockIdx.y * 128;

    const int lrow = t >> 1;
    const int lk4  = (t & 1) * 4;
    const float* Ag = X + (size_t)(row0 + lrow) * CC + lk4;
    const float* Bg = W + (size_t)(col0 + lrow) * CC + lk4;

    float4 afrag = *(const float4*)Ag;
    float4 bfrag = *(const float4*)Bg;

    As[0][lk4 + 0][lrow] = afrag.x;
    As[0][lk4 + 1][lrow] = afrag.y;
    As[0][lk4 + 2][lrow] = afrag.z;
    As[0][lk4 + 3][lrow] = afrag.w;
    Bs[0][lk4 + 0][lrow] = bfrag.x;
    Bs[0][lk4 + 1][lrow] = bfrag.y;
    Bs[0][lk4 + 2][lrow] = bfrag.z;
    Bs[0][lk4 + 3][lrow] = bfrag.w;
    __syncthreads();

    float acc[8][8];
    #pragma unroll
    for (int i = 0; i < 8; ++i)
        #pragma unroll
        for (int j = 0; j < 8; ++j) acc[i][j] = 0.0f;

    #pragma unroll 1
    for (int kt = 0; kt < 32; ++kt) {
        int buf = kt & 1;
        if (kt < 31) {
            afrag = *(const float4*)(Ag + (kt + 1) * 8);
            bfrag = *(const float4*)(Bg + (kt + 1) * 8);
        }

        #pragma unroll
        for (int kk = 0; kk < 8; ++kk) {
            float4 a0 = *(const float4*)&As[buf][kk][ty * 8];
            float4 a1 = *(const float4*)&As[buf][kk][ty * 8 + 4];
            float4 b0 = *(const float4*)&Bs[buf][kk][tx * 8];
            float4 b1 = *(const float4*)&Bs[buf][kk][tx * 8 + 4];
            float av[8] = {a0.x, a0.y, a0.z, a0.w, a1.x, a1.y, a1.z, a1.w};
            float bv[8] = {b0.x, b0.y, b0.z, b0.w, b1.x, b1.y, b1.z, b1.w};
            #pragma unroll
            for (int i = 0; i < 8; ++i)
                #pragma unroll
                for (int j = 0; j < 8; ++j)
                    acc[i][j] = fmaf(av[i], bv[j], acc[i][j]);
        }

        if (kt < 31) {
            int nb = buf ^ 1;
            As[nb][lk4 + 0][lrow] = afrag.x;
            As[nb][lk4 + 1][lrow] = afrag.y;
            As[nb][lk4 + 2][lrow] = afrag.z;
            As[nb][lk4 + 3][lrow] = afrag.w;
            Bs[nb][lk4 + 0][lrow] = bfrag.x;
            Bs[nb][lk4 + 1][lrow] = bfrag.y;
            Bs[nb][lk4 + 2][lrow] = bfrag.z;
            Bs[nb][lk4 + 3][lrow] = bfrag.w;
            __syncthreads();
        }
    }

    float bb[8], tf[8];
    #pragma unroll
    for (int j = 0; j < 8; ++j) {
        int c = col0 + tx * 8 + j;
        bb[j] = bias[c];
        if (ADDTF) tf[j] = g_tf[c];
    }

    #pragma unroll
    for (int i = 0; i < 8; ++i) {
        int r = row0 + ty * 8 + i;
        float o[8];
        #pragma unroll
        for (int j = 0; j < 8; ++j) {
            float v = acc[i][j] + bb[j];
            if (ACT)   v = (v >= 0.0f) ? v : 0.1f * v;
            if (ADDTF) v = v + tf[j];
            o[j] = v;
        }
        float4* yp = (float4*)(Y + (size_t)r * CC + col0 + tx * 8);
        yp[0] = make_float4(o[0], o[1], o[2], o[3]);
        yp[1] = make_float4(o[4], o[5], o[6], o[7]);
    }
}

// ---------------------------------------------------------------------------
extern "C" void kernel_launch(void* const* d_in, const int* in_sizes, int n_in,
                              void* d_out, int out_size) {
    const int*   node_c     = (const int*)d_in[0];
    const int*   cond_c     = (const int*)d_in[1];
    const float* cond_feats = (const float*)d_in[2];
    const float* t          = (const float*)d_in[3];
    const float* W_proj     = (const float*)d_in[4];
    const float* b_proj     = (const float*)d_in[5];
    const float* W_l1       = (const float*)d_in[6];
    const float* b_l1       = (const float*)d_in[7];
    const float* W_l2       = (const float*)d_in[8];
    const float* b_l2       = (const float*)d_in[9];
    const float* W_t1       = (const float*)d_in[10];
    const float* b_t1       = (const float*)d_in[11];
    const float* W_t2       = (const float*)d_in[12];
    const float* b_t2       = (const float*)d_in[13];
    float* out = (float*)d_out;

    float* h1; cudaGetSymbolAddress((void**)&h1, g_h1);
    float* h2; cudaGetSymbolAddress((void**)&h2, g_h2);
    float* fa; cudaGetSymbolAddress((void**)&fa, g_favg);

    k_tfeats<<<1, 256>>>(t, W_t1, b_t1, W_t2, b_t2);

    dim3 gknn(NN / 256, GG);       // 64 x 16 blocks, 128 threads (2 nodes/thread)
    k_knn<<<gknn, 128>>>(node_c, cond_c);

    k_merge<<<NN / 8, 256>>>(cond_feats);

    dim3 gg(NN / 128, CC / 128);   // 128 x 2 = 256 blocks
    k_gemm<0, 0><<<gg, 256>>>(fa, W_proj, b_proj, h1);
    k_gemm<1, 0><<<gg, 256>>>(h1, W_l1, b_l1, h2);
    k_gemm<0, 1><<<gg, 256>>>(h2, W_l2, b_l2, out);

    (void)in_sizes; (void)n_in; (void)out_size;
}